// round 1
// baseline (speedup 1.0000x reference)
#include <cuda_runtime.h>
#include <math.h>

// Problem constants
// B=128, N=NONGT=36, D=1024, H=16, DG=64, PE=64
// Rows M = B*N = 4608 ; fused GEMM cols = 3*1024 = 3072
#define GM 4608
#define GN 3072
#define GK 1024

// ---------------- device scratch (no allocations allowed) ----------------
__device__ __align__(16) float g_Wcat[GK * GN];        // 12.6 MB  B-matrix, K-major rows
__device__ __align__(16) float g_bcat[GN];             // fused col bias (bq|bk|0)
__device__ __align__(16) float g_qkv[GM * GN];         // 56.6 MB  [q|k|vproj]
__device__ __align__(16) float g_poslog[4608 * 16 * 36]; // 10.6 MB poslog[b][n][h][m]

// ---------------- K0: pack weights ----------------
// Wcat[k][col] = Wsrc[j*1024 + k]  (j = col % 1024, seg = col / 1024 -> Wq, Wk, Wout)
__global__ void pack_weights(const float* __restrict__ Wq, const float* __restrict__ Wk,
                             const float* __restrict__ Wout,
                             const float* __restrict__ bq, const float* __restrict__ bk) {
    __shared__ float tile[32][33];
    int col0 = blockIdx.x * 32;     // output column block (j-dim in source)
    int k0   = blockIdx.y * 32;     // k block
    int seg  = col0 >> 10;
    const float* src = (seg == 0) ? Wq : (seg == 1) ? Wk : Wout;
    int j0 = col0 & 1023;
    for (int i = threadIdx.y; i < 32; i += 8)
        tile[i][threadIdx.x] = src[(size_t)(j0 + i) * 1024 + k0 + threadIdx.x];
    __syncthreads();
    for (int i = threadIdx.y; i < 32; i += 8)
        g_Wcat[(size_t)(k0 + i) * GN + col0 + threadIdx.x] = tile[threadIdx.x][i];
    if (blockIdx.y == 0 && threadIdx.y == 0) {
        float bv = 0.f;
        if (seg == 0) bv = bq[j0 + threadIdx.x];
        else if (seg == 1) bv = bk[j0 + threadIdx.x];
        g_bcat[col0 + threadIdx.x] = bv;
    }
}

// ---------------- K1: fused SGEMM  qkv = X @ Wcat + bcat ----------------
// 128x128 block tile, BK=16, 8x8 per-thread tile, 256 threads.
__global__ __launch_bounds__(256, 2)
void sgemm_qkv(const float* __restrict__ A) {
    __shared__ float As[16][128];
    __shared__ float Bs[16][128];
    int t  = threadIdx.x;
    int bm = blockIdx.y * 128;
    int bn = blockIdx.x * 128;
    int ty = t >> 4, tx = t & 15;
    int arow = t >> 2, acol = (t & 3) << 2;   // A: 64 rows x 16 k per pass
    int brow = t >> 5, bcol = (t & 31) << 2;  // B: 8 k x 128 n per pass

    float acc[8][8];
#pragma unroll
    for (int i = 0; i < 8; i++)
#pragma unroll
        for (int j = 0; j < 8; j++) acc[i][j] = 0.f;

    for (int k0 = 0; k0 < GK; k0 += 16) {
#pragma unroll
        for (int pass = 0; pass < 2; pass++) {
            int r = arow + pass * 64;
            float4 v = *(const float4*)&A[(size_t)(bm + r) * GK + k0 + acol];
            As[acol + 0][r] = v.x; As[acol + 1][r] = v.y;
            As[acol + 2][r] = v.z; As[acol + 3][r] = v.w;
        }
#pragma unroll
        for (int pass = 0; pass < 2; pass++) {
            int r = brow + pass * 8;
            *(float4*)&Bs[r][bcol] = *(const float4*)&g_Wcat[(size_t)(k0 + r) * GN + bn + bcol];
        }
        __syncthreads();
#pragma unroll
        for (int kk = 0; kk < 16; kk++) {
            float ar[8], br[8];
            *(float4*)&ar[0] = *(const float4*)&As[kk][ty * 8];
            *(float4*)&ar[4] = *(const float4*)&As[kk][ty * 8 + 4];
            *(float4*)&br[0] = *(const float4*)&Bs[kk][tx * 8];
            *(float4*)&br[4] = *(const float4*)&Bs[kk][tx * 8 + 4];
#pragma unroll
            for (int i = 0; i < 8; i++)
#pragma unroll
                for (int j = 0; j < 8; j++) acc[i][j] += ar[i] * br[j];
        }
        __syncthreads();
    }
#pragma unroll
    for (int i = 0; i < 8; i++) {
        int row = bm + ty * 8 + i;
#pragma unroll
        for (int j4 = 0; j4 < 2; j4++) {
            int col = bn + tx * 8 + j4 * 4;
            float4 o;
            o.x = acc[i][j4 * 4 + 0] + g_bcat[col + 0];
            o.y = acc[i][j4 * 4 + 1] + g_bcat[col + 1];
            o.z = acc[i][j4 * 4 + 2] + g_bcat[col + 2];
            o.w = acc[i][j4 * 4 + 3] + g_bcat[col + 3];
            *(float4*)&g_qkv[(size_t)row * GN + col] = o;
        }
    }
}

// ---------------- K2: pos = log(max(relu(PE @ Wpos^T + bpos), 1e-6)) ----------------
// Block = 128 rows (b,n,m triples) x all 16 heads. 128 threads, one row each.
__global__ __launch_bounds__(128)
void pos_kernel(const float* __restrict__ PEmb, const float* __restrict__ Wpos,
                const float* __restrict__ bpos) {
    __shared__ float pe[128 * 65];   // padded rows: conflict-free
    __shared__ float wpT[64 * 17];   // wpT[p][h], padded
    __shared__ float bp[16];
    int t = threadIdx.x;
    size_t base = (size_t)blockIdx.x * 128 * 64;
    for (int i = t; i < 128 * 64; i += 128)
        pe[(i >> 6) * 65 + (i & 63)] = PEmb[base + i];
    for (int i = t; i < 1024; i += 128)
        wpT[(i & 63) * 17 + (i >> 6)] = Wpos[i];   // Wpos[h*64+p] -> wpT[p*17+h]
    if (t < 16) bp[t] = bpos[t];
    __syncthreads();

    float s[16];
#pragma unroll
    for (int h = 0; h < 16; h++) s[h] = 0.f;
    const float* pr = &pe[t * 65];
#pragma unroll 8
    for (int p = 0; p < 64; p++) {
        float a = pr[p];
        const float* w = &wpT[p * 17];
#pragma unroll
        for (int h = 0; h < 16; h++) s[h] += a * w[h];
    }
    int r  = blockIdx.x * 128 + t;    // row = (b*36+n)*36 + m
    int bn = r / 36, m = r % 36;
    size_t ob = (size_t)bn * 16 * 36 + m;
#pragma unroll
    for (int h = 0; h < 16; h++) {
        float v = fmaxf(s[h] + bp[h], 1e-6f);   // relu then clamp 1e-6 == max(v,1e-6)
        g_poslog[ob + (size_t)h * 36] = logf(v);
    }
}

// ---------------- K3: attention per (b,h) ----------------
__global__ __launch_bounds__(256)
void attn_kernel(const int* __restrict__ adj, const float* __restrict__ lbias,
                 const float* __restrict__ bout, float* __restrict__ out) {
    __shared__ float qh[36][64];
    __shared__ float khT[64][40];   // transposed K head, padded row
    __shared__ float vp[36][64];
    __shared__ float att[36 * 36];
    int b = blockIdx.x >> 4, h = blockIdx.x & 15;
    int t = threadIdx.x;

    const float* base = g_qkv + (size_t)b * 36 * GN + h * 64;
    for (int i = t; i < 576; i += 256) {
        int n = i >> 4, c = (i & 15) << 2;
        const float* rp = base + (size_t)n * GN + c;
        float4 q4 = *(const float4*)rp;
        float4 k4 = *(const float4*)(rp + 1024);
        float4 v4 = *(const float4*)(rp + 2048);
        *(float4*)&qh[n][c] = q4;
        khT[c + 0][n] = k4.x; khT[c + 1][n] = k4.y;
        khT[c + 2][n] = k4.z; khT[c + 3][n] = k4.w;
        *(float4*)&vp[n][c] = v4;
    }
    __syncthreads();

    // logits: q.k/8 + poslog + mask + label_bias
    const float* pl = g_poslog + (size_t)b * 36 * 16 * 36 + (size_t)h * 36;
    for (int o = t; o < 324; o += 256) {          // 36 n x 9 groups of 4 m
        int n = o / 9, m0 = (o % 9) << 2;
        float4 s = make_float4(0.f, 0.f, 0.f, 0.f);
#pragma unroll
        for (int d = 0; d < 64; d++) {
            float a = qh[n][d];
            float4 kv = *(const float4*)&khT[d][m0];
            s.x += a * kv.x; s.y += a * kv.y; s.z += a * kv.z; s.w += a * kv.w;
        }
        float sv[4] = {s.x, s.y, s.z, s.w};
        int rowg = (b * 36 + n) * 36;
#pragma unroll
        for (int r2 = 0; r2 < 4; r2++) {
            int m = m0 + r2;
            int gi = rowg + m;
            float logit = (adj[gi] > 0)
                          ? (sv[r2] * 0.125f + pl[(size_t)n * 16 * 36 + m])
                          : -9e15f;
            att[n * 36 + m] = logit + lbias[gi];
        }
    }
    __syncthreads();

    // softmax over 36 (one warp per row, lanes cover m and m+32)
    int warp = t >> 5, lane = t & 31;
    for (int n = warp; n < 36; n += 8) {
        float x1 = att[n * 36 + lane];
        float x2 = (lane < 4) ? att[n * 36 + 32 + lane] : -3e38f;
        float mx = fmaxf(x1, x2);
#pragma unroll
        for (int off = 16; off > 0; off >>= 1)
            mx = fmaxf(mx, __shfl_xor_sync(0xffffffffu, mx, off));
        float e1 = expf(x1 - mx);
        float e2 = (lane < 4) ? expf(x2 - mx) : 0.f;
        float sum = e1 + e2;
#pragma unroll
        for (int off = 16; off > 0; off >>= 1)
            sum += __shfl_xor_sync(0xffffffffu, sum, off);
        float inv = 1.f / sum;
        att[n * 36 + lane] = e1 * inv;
        if (lane < 4) att[n * 36 + 32 + lane] = e2 * inv;
    }
    __syncthreads();

    // out[b,n,h*64+e] = sum_m att[n][m] * vproj[m][e] + bout
    const float* bo = bout + h * 64;
    for (int o = t; o < 576; o += 256) {
        int n = o >> 4, e0 = (o & 15) << 2;
        float4 acc4 = *(const float4*)&bo[e0];
#pragma unroll
        for (int m = 0; m < 36; m++) {
            float a = att[n * 36 + m];
            float4 v4 = *(const float4*)&vp[m][e0];
            acc4.x += a * v4.x; acc4.y += a * v4.y;
            acc4.z += a * v4.z; acc4.w += a * v4.w;
        }
        *(float4*)&out[(size_t)(b * 36 + n) * 1024 + h * 64 + e0] = acc4;
    }
}

// ---------------- launch ----------------
extern "C" void kernel_launch(void* const* d_in, const int* in_sizes, int n_in,
                              void* d_out, int out_size) {
    const float* roi  = (const float*)d_in[0];
    const int*   adj  = (const int*)  d_in[1];
    const float* pe   = (const float*)d_in[2];
    const float* lb   = (const float*)d_in[3];
    const float* Wq   = (const float*)d_in[4];
    const float* bq   = (const float*)d_in[5];
    const float* Wk   = (const float*)d_in[6];
    const float* bk   = (const float*)d_in[7];
    const float* Wpos = (const float*)d_in[8];
    const float* bpos = (const float*)d_in[9];
    const float* Wout = (const float*)d_in[10];
    const float* bout = (const float*)d_in[11];
    float* out = (float*)d_out;

    dim3 g0(GN / 32, GK / 32), b0(32, 8);
    pack_weights<<<g0, b0>>>(Wq, Wk, Wout, bq, bk);

    dim3 g1(GN / 128, GM / 128);
    sgemm_qkv<<<g1, 256>>>(roi);

    pos_kernel<<<(4608 * 36) / 128, 128>>>(pe, Wpos, bpos);

    attn_kernel<<<128 * 16, 256>>>(adj, lb, bout, out);
}

// round 3
// speedup vs baseline: 2.0739x; 2.0739x over previous
#include <cuda_runtime.h>
#include <cuda_fp16.h>
#include <math.h>
#include <cstdint>

// B=128, N=NONGT=36, D=1024, H=16, DG=64, PE=64
#define GM 4608      // rows = B*N
#define GN 3072      // cols = 3*1024  [q|k|vproj]
#define GK 1024      // inner dim (fp32)
#define KP 3072      // split K' = 3*GK (fp16 segments [hh|hl|lh])
#define BM 128
#define BN 128
#define BK 64
#define NK (KP / BK)   // 48

// ---------------- device scratch ----------------
__device__ __align__(16) __half g_Ah[(size_t)GM * KP];   // 28.3 MB [Ah|Ah|Al]
__device__ __align__(16) __half g_Bh[(size_t)GN * KP];   // 18.9 MB [Bh|Bl|Bh], [N,K'] K-major
__device__ __align__(16) float g_bcat[GN];
__device__ __align__(16) float g_qkv[(size_t)GM * GN];   // 56.6 MB
__device__ __align__(16) float g_poslog[4608 * 16 * 36]; // 10.6 MB

// ---------------- helpers ----------------
__device__ __forceinline__ uint32_t smem_u32(const void* p) {
    uint32_t a;
    asm("{ .reg .u64 t; cvta.to.shared.u64 t, %1; cvt.u32.u64 %0, t; }" : "=r"(a) : "l"(p));
    return a;
}
__device__ __forceinline__ void cp16(uint32_t d, const void* s) {
    asm volatile("cp.async.cg.shared.global [%0], [%1], 16;" :: "r"(d), "l"(s));
}

// ---------------- K0a: split A (fp32 -> fp16 h/l) into [Ah|Ah|Al] ----------------
__global__ __launch_bounds__(256) void conv_A(const float* __restrict__ A) {
    int i = blockIdx.x * 256 + threadIdx.x;     // float4 index, GM*GK/4 total
    float4 v = ((const float4*)A)[i];
    int row = i >> 8;                            // 256 float4 per row of 1024
    int c4 = (i & 255) << 2;
    float x[4] = {v.x, v.y, v.z, v.w};
    __half h[4], l[4];
#pragma unroll
    for (int j = 0; j < 4; j++) {
        h[j] = __float2half_rn(x[j]);
        l[j] = __float2half_rn(x[j] - __half2float(h[j]));
    }
    __half2 h01 = __halves2half2(h[0], h[1]), h23 = __halves2half2(h[2], h[3]);
    __half2 l01 = __halves2half2(l[0], l[1]), l23 = __halves2half2(l[2], l[3]);
    size_t base = (size_t)row * KP + c4;
    *(__half2*)&g_Ah[base]        = h01; *(__half2*)&g_Ah[base + 2]    = h23;
    *(__half2*)&g_Ah[base + 1024] = h01; *(__half2*)&g_Ah[base + 1026] = h23;
    *(__half2*)&g_Ah[base + 2048] = l01; *(__half2*)&g_Ah[base + 2050] = l23;
}

// ---------------- K0b: split weights into [Bh|Bl|Bh] ----------------
__global__ __launch_bounds__(256) void conv_B(const float* __restrict__ Wq,
                                              const float* __restrict__ Wk,
                                              const float* __restrict__ Wout) {
    int i = blockIdx.x * 256 + threadIdx.x;     // float4 index, GN*GK/4 total
    int row = i >> 8;                            // n in [0,3072)
    int c4 = (i & 255) << 2;
    const float* src = (row < 1024) ? (Wq + (size_t)row * 1024)
                     : (row < 2048) ? (Wk + (size_t)(row - 1024) * 1024)
                                    : (Wout + (size_t)(row - 2048) * 1024);
    float4 v = *(const float4*)(src + c4);
    float x[4] = {v.x, v.y, v.z, v.w};
    __half h[4], l[4];
#pragma unroll
    for (int j = 0; j < 4; j++) {
        h[j] = __float2half_rn(x[j]);
        l[j] = __float2half_rn(x[j] - __half2float(h[j]));
    }
    __half2 h01 = __halves2half2(h[0], h[1]), h23 = __halves2half2(h[2], h[3]);
    __half2 l01 = __halves2half2(l[0], l[1]), l23 = __halves2half2(l[2], l[3]);
    size_t base = (size_t)row * KP + c4;
    *(__half2*)&g_Bh[base]        = h01; *(__half2*)&g_Bh[base + 2]    = h23;
    *(__half2*)&g_Bh[base + 1024] = l01; *(__half2*)&g_Bh[base + 1026] = l23;
    *(__half2*)&g_Bh[base + 2048] = h01; *(__half2*)&g_Bh[base + 2050] = h23;
}

__global__ void fill_bcat(const float* __restrict__ bq, const float* __restrict__ bk) {
    int n = blockIdx.x * 256 + threadIdx.x;
    float v = 0.f;
    if (n < 1024) v = bq[n];
    else if (n < 2048) v = bk[n - 1024];
    g_bcat[n] = v;
}

// ---------------- K1: HMMA GEMM  qkv = A' @ B'^T + bcat ----------------
// Per stage: A 128x64 fp16 (16KB, 128B rows, XOR-swizzled) + B 128x64 fp16 (16KB).
// 2 stages = 64KB dynamic smem. 8 warps: 4(M) x 2(N), warp tile 32x64.
__device__ __forceinline__ void load_tile(uint32_t base, const __half* Ag, const __half* Bg, int t) {
#pragma unroll
    for (int i = 0; i < 4; i++) {
        int c = t + i * 256;
        int row = c >> 3, k = c & 7;
        uint32_t sw = row * 128 + ((k ^ (row & 7)) << 4);
        cp16(base + sw, (const char*)(Ag + (size_t)row * KP) + k * 16);
        cp16(base + 16384 + sw, (const char*)(Bg + (size_t)row * KP) + k * 16);
    }
    asm volatile("cp.async.commit_group;" ::: "memory");
}

__global__ __launch_bounds__(256, 2) void gemm_hmma() {
    extern __shared__ char smem[];
    uint32_t sb = smem_u32(smem);
    int t = threadIdx.x, lane = t & 31, wid = t >> 5;
    int bm = blockIdx.y * BM, bn = blockIdx.x * BN;
    int wm = wid >> 1, wn = wid & 1;

    const __half* Ag = g_Ah + (size_t)bm * KP;
    const __half* Bg = g_Bh + (size_t)bn * KP;

    float acc[2][8][4];
#pragma unroll
    for (int mt = 0; mt < 2; mt++)
#pragma unroll
        for (int nt = 0; nt < 8; nt++)
#pragma unroll
            for (int j = 0; j < 4; j++) acc[mt][nt][j] = 0.f;

    // per-thread ldmatrix address components
    int a_row = wm * 32 + (lane & 7) + ((lane >> 3) & 1) * 8;   // + mt*16
    int a_ch  = (lane >> 4);                                     // + ks*2
    int b_row = wn * 64 + (lane & 7) + ((lane >> 4) & 1) * 8;   // + ntp*16
    int b_ch  = (lane >> 3) & 1;                                 // + ks*2

    load_tile(sb, Ag, Bg, t);

    for (int kt = 0; kt < NK; kt++) {
        if (kt + 1 < NK) {
            load_tile(sb + ((kt + 1) & 1) * 32768, Ag + (size_t)(kt + 1) * BK,
                      Bg + (size_t)(kt + 1) * BK, t);
            asm volatile("cp.async.wait_group 1;" ::: "memory");
        } else {
            asm volatile("cp.async.wait_group 0;" ::: "memory");
        }
        __syncthreads();

        uint32_t base = sb + (kt & 1) * 32768;
#pragma unroll
        for (int ks = 0; ks < 4; ks++) {
            uint32_t af[2][4];
#pragma unroll
            for (int mt = 0; mt < 2; mt++) {
                int r = a_row + mt * 16;
                uint32_t ad = base + r * 128 + (((ks * 2 + a_ch) ^ (r & 7)) << 4);
                asm volatile("ldmatrix.sync.aligned.m8n8.x4.shared.b16 {%0,%1,%2,%3}, [%4];"
                             : "=r"(af[mt][0]), "=r"(af[mt][1]), "=r"(af[mt][2]), "=r"(af[mt][3])
                             : "r"(ad));
            }
            uint32_t bf[8][2];
#pragma unroll
            for (int ntp = 0; ntp < 4; ntp++) {
                int r = b_row + ntp * 16;
                uint32_t ad = base + 16384 + r * 128 + (((ks * 2 + b_ch) ^ (r & 7)) << 4);
                asm volatile("ldmatrix.sync.aligned.m8n8.x4.shared.b16 {%0,%1,%2,%3}, [%4];"
                             : "=r"(bf[ntp * 2][0]), "=r"(bf[ntp * 2][1]),
                               "=r"(bf[ntp * 2 + 1][0]), "=r"(bf[ntp * 2 + 1][1])
                             : "r"(ad));
            }
#pragma unroll
            for (int mt = 0; mt < 2; mt++)
#pragma unroll
                for (int nt = 0; nt < 8; nt++) {
                    asm volatile(
                        "mma.sync.aligned.m16n8k16.row.col.f32.f16.f16.f32 "
                        "{%0,%1,%2,%3}, {%4,%5,%6,%7}, {%8,%9}, {%0,%1,%2,%3};"
                        : "+f"(acc[mt][nt][0]), "+f"(acc[mt][nt][1]),
                          "+f"(acc[mt][nt][2]), "+f"(acc[mt][nt][3])
                        : "r"(af[mt][0]), "r"(af[mt][1]), "r"(af[mt][2]), "r"(af[mt][3]),
                          "r"(bf[nt][0]), "r"(bf[nt][1]));
                }
        }
        __syncthreads();
    }

    // epilogue: direct float2 stores + bias
#pragma unroll
    for (int mt = 0; mt < 2; mt++)
#pragma unroll
        for (int h2 = 0; h2 < 2; h2++) {
            int row = bm + wm * 32 + mt * 16 + (lane >> 2) + h2 * 8;
#pragma unroll
            for (int nt = 0; nt < 8; nt++) {
                int col = bn + wn * 64 + nt * 8 + (lane & 3) * 2;
                float2 o;
                o.x = acc[mt][nt][h2 * 2 + 0] + g_bcat[col + 0];
                o.y = acc[mt][nt][h2 * 2 + 1] + g_bcat[col + 1];
                *(float2*)&g_qkv[(size_t)row * GN + col] = o;
            }
        }
}

// ---------------- K2: pos = log(max(relu(PE @ Wpos^T + bpos), 1e-6)) ----------------
__global__ __launch_bounds__(128)
void pos_kernel(const float* __restrict__ PEmb, const float* __restrict__ Wpos,
                const float* __restrict__ bpos) {
    __shared__ float pe[128 * 65];
    __shared__ float wpT[64 * 17];
    __shared__ float bp[16];
    int t = threadIdx.x;
    size_t base = (size_t)blockIdx.x * 128 * 64;
    for (int i = t; i < 128 * 64; i += 128)
        pe[(i >> 6) * 65 + (i & 63)] = PEmb[base + i];
    for (int i = t; i < 1024; i += 128)
        wpT[(i & 63) * 17 + (i >> 6)] = Wpos[i];
    if (t < 16) bp[t] = bpos[t];
    __syncthreads();

    float s[16];
#pragma unroll
    for (int h = 0; h < 16; h++) s[h] = 0.f;
    const float* pr = &pe[t * 65];
#pragma unroll 8
    for (int p = 0; p < 64; p++) {
        float a = pr[p];
        const float* w = &wpT[p * 17];
#pragma unroll
        for (int h = 0; h < 16; h++) s[h] += a * w[h];
    }
    int r = blockIdx.x * 128 + t;
    int bn = r / 36, m = r % 36;
    size_t ob = (size_t)bn * 16 * 36 + m;
#pragma unroll
    for (int h = 0; h < 16; h++) {
        float v = fmaxf(s[h] + bp[h], 1e-6f);
        g_poslog[ob + (size_t)h * 36] = logf(v);
    }
}

// ---------------- K3: attention per (b,h) ----------------
__global__ __launch_bounds__(256)
void attn_kernel(const int* __restrict__ adj, const float* __restrict__ lbias,
                 const float* __restrict__ bout, float* __restrict__ out) {
    __shared__ float qh[36][64];
    __shared__ float khT[64][40];
    __shared__ float vp[36][64];
    __shared__ float att[36 * 36];
    int b = blockIdx.x >> 4, h = blockIdx.x & 15;
    int t = threadIdx.x;

    const float* base = g_qkv + (size_t)b * 36 * GN + h * 64;
    for (int i = t; i < 576; i += 256) {
        int n = i >> 4, c = (i & 15) << 2;
        const float* rp = base + (size_t)n * GN + c;
        float4 q4 = *(const float4*)rp;
        float4 k4 = *(const float4*)(rp + 1024);
        float4 v4 = *(const float4*)(rp + 2048);
        *(float4*)&qh[n][c] = q4;
        khT[c + 0][n] = k4.x; khT[c + 1][n] = k4.y;
        khT[c + 2][n] = k4.z; khT[c + 3][n] = k4.w;
        *(float4*)&vp[n][c] = v4;
    }
    __syncthreads();

    const float* pl = g_poslog + (size_t)b * 36 * 16 * 36 + (size_t)h * 36;
    for (int o = t; o < 324; o += 256) {
        int n = o / 9, m0 = (o % 9) << 2;
        float4 s = make_float4(0.f, 0.f, 0.f, 0.f);
#pragma unroll
        for (int d = 0; d < 64; d++) {
            float a = qh[n][d];
            float4 kv = *(const float4*)&khT[d][m0];
            s.x += a * kv.x; s.y += a * kv.y; s.z += a * kv.z; s.w += a * kv.w;
        }
        float sv[4] = {s.x, s.y, s.z, s.w};
        int rowg = (b * 36 + n) * 36;
#pragma unroll
        for (int r2 = 0; r2 < 4; r2++) {
            int m = m0 + r2;
            int gi = rowg + m;
            float logit = (adj[gi] > 0)
                          ? (sv[r2] * 0.125f + pl[(size_t)n * 16 * 36 + m])
                          : -9e15f;
            att[n * 36 + m] = logit + lbias[gi];
        }
    }
    __syncthreads();

    int warp = t >> 5, lane = t & 31;
    for (int n = warp; n < 36; n += 8) {
        float x1 = att[n * 36 + lane];
        float x2 = (lane < 4) ? att[n * 36 + 32 + lane] : -3e38f;
        float mx = fmaxf(x1, x2);
#pragma unroll
        for (int off = 16; off > 0; off >>= 1)
            mx = fmaxf(mx, __shfl_xor_sync(0xffffffffu, mx, off));
        float e1 = expf(x1 - mx);
        float e2 = (lane < 4) ? expf(x2 - mx) : 0.f;
        float sum = e1 + e2;
#pragma unroll
        for (int off = 16; off > 0; off >>= 1)
            sum += __shfl_xor_sync(0xffffffffu, sum, off);
        float inv = 1.f / sum;
        att[n * 36 + lane] = e1 * inv;
        if (lane < 4) att[n * 36 + 32 + lane] = e2 * inv;
    }
    __syncthreads();

    const float* bo = bout + h * 64;
    for (int o = t; o < 576; o += 256) {
        int n = o >> 4, e0 = (o & 15) << 2;
        float4 acc4 = *(const float4*)&bo[e0];
#pragma unroll
        for (int m = 0; m < 36; m++) {
            float a = att[n * 36 + m];
            float4 v4 = *(const float4*)&vp[m][e0];
            acc4.x += a * v4.x; acc4.y += a * v4.y;
            acc4.z += a * v4.z; acc4.w += a * v4.w;
        }
        *(float4*)&out[(size_t)(b * 36 + n) * 1024 + h * 64 + e0] = acc4;
    }
}

// ---------------- launch ----------------
extern "C" void kernel_launch(void* const* d_in, const int* in_sizes, int n_in,
                              void* d_out, int out_size) {
    const float* roi  = (const float*)d_in[0];
    const int*   adj  = (const int*)  d_in[1];
    const float* pe   = (const float*)d_in[2];
    const float* lb   = (const float*)d_in[3];
    const float* Wq   = (const float*)d_in[4];
    const float* bq   = (const float*)d_in[5];
    const float* Wk   = (const float*)d_in[6];
    const float* bk   = (const float*)d_in[7];
    const float* Wpos = (const float*)d_in[8];
    const float* bpos = (const float*)d_in[9];
    const float* Wout = (const float*)d_in[10];
    const float* bout = (const float*)d_in[11];
    float* out = (float*)d_out;

    static int smem_set = 0;
    if (!smem_set) {
        cudaFuncSetAttribute(gemm_hmma, cudaFuncAttributeMaxDynamicSharedMemorySize, 65536);
        smem_set = 1;
    }

    conv_A<<<GM * GK / 4 / 256, 256>>>(roi);
    conv_B<<<GN * GK / 4 / 256, 256>>>(Wq, Wk, Wout);
    fill_bcat<<<GN / 256, 256>>>(bq, bk);

    dim3 gg(GN / BN, GM / BM);
    gemm_hmma<<<gg, 256, 65536>>>();

    pos_kernel<<<(4608 * 36) / 128, 128>>>(pe, Wpos, bpos);

    attn_kernel<<<128 * 16, 256>>>(adj, lb, bout, out);
}

// round 4
// speedup vs baseline: 2.1681x; 1.0455x over previous
#include <cuda_runtime.h>
#include <cuda_fp16.h>
#include <math.h>
#include <cstdint>

// B=128, N=NONGT=36, D=1024, H=16, DG=64, PE=64
#define GM 4608      // rows = B*N
#define GN 3072      // cols = 3*1024  [q|k|vproj]
#define GK 1024      // inner dim (fp32)
#define KP 3072      // split K' = 3*GK (fp16 segments [hh|hl|lh])
#define BM 128
#define BN 256
#define BK 64
#define NK (KP / BK)   // 48
#define STG 49152      // stage stride: A 16KB + B 32KB
#define NSTAGE 3

// ---------------- device scratch ----------------
__device__ __align__(16) __half g_Ah[(size_t)GM * KP];   // 28.3 MB [Ah|Ah|Al]
__device__ __align__(16) __half g_Bh[(size_t)GN * KP];   // 18.9 MB [Bh|Bl|Bh], [N,K'] K-major
__device__ __align__(16) float g_bcat[GN];
__device__ __align__(16) float g_qkv[(size_t)GM * GN];   // 56.6 MB
__device__ __align__(16) float g_poslog[4608 * 16 * 36]; // 10.6 MB

// ---------------- helpers ----------------
__device__ __forceinline__ uint32_t smem_u32(const void* p) {
    uint32_t a;
    asm("{ .reg .u64 t; cvta.to.shared.u64 t, %1; cvt.u32.u64 %0, t; }" : "=r"(a) : "l"(p));
    return a;
}
__device__ __forceinline__ void cp16(uint32_t d, const void* s) {
    asm volatile("cp.async.cg.shared.global [%0], [%1], 16;" :: "r"(d), "l"(s));
}

// ---------------- K0a: split A (fp32 -> fp16 h/l) into [Ah|Ah|Al] ----------------
__global__ __launch_bounds__(256) void conv_A(const float* __restrict__ A) {
    int i = blockIdx.x * 256 + threadIdx.x;
    float4 v = ((const float4*)A)[i];
    int row = i >> 8;
    int c4 = (i & 255) << 2;
    float x[4] = {v.x, v.y, v.z, v.w};
    __half h[4], l[4];
#pragma unroll
    for (int j = 0; j < 4; j++) {
        h[j] = __float2half_rn(x[j]);
        l[j] = __float2half_rn(x[j] - __half2float(h[j]));
    }
    __half2 h01 = __halves2half2(h[0], h[1]), h23 = __halves2half2(h[2], h[3]);
    __half2 l01 = __halves2half2(l[0], l[1]), l23 = __halves2half2(l[2], l[3]);
    size_t base = (size_t)row * KP + c4;
    *(__half2*)&g_Ah[base]        = h01; *(__half2*)&g_Ah[base + 2]    = h23;
    *(__half2*)&g_Ah[base + 1024] = h01; *(__half2*)&g_Ah[base + 1026] = h23;
    *(__half2*)&g_Ah[base + 2048] = l01; *(__half2*)&g_Ah[base + 2050] = l23;
}

// ---------------- K0b: split weights into [Bh|Bl|Bh] ----------------
__global__ __launch_bounds__(256) void conv_B(const float* __restrict__ Wq,
                                              const float* __restrict__ Wk,
                                              const float* __restrict__ Wout) {
    int i = blockIdx.x * 256 + threadIdx.x;
    int row = i >> 8;
    int c4 = (i & 255) << 2;
    const float* src = (row < 1024) ? (Wq + (size_t)row * 1024)
                     : (row < 2048) ? (Wk + (size_t)(row - 1024) * 1024)
                                    : (Wout + (size_t)(row - 2048) * 1024);
    float4 v = *(const float4*)(src + c4);
    float x[4] = {v.x, v.y, v.z, v.w};
    __half h[4], l[4];
#pragma unroll
    for (int j = 0; j < 4; j++) {
        h[j] = __float2half_rn(x[j]);
        l[j] = __float2half_rn(x[j] - __half2float(h[j]));
    }
    __half2 h01 = __halves2half2(h[0], h[1]), h23 = __halves2half2(h[2], h[3]);
    __half2 l01 = __halves2half2(l[0], l[1]), l23 = __halves2half2(l[2], l[3]);
    size_t base = (size_t)row * KP + c4;
    *(__half2*)&g_Bh[base]        = h01; *(__half2*)&g_Bh[base + 2]    = h23;
    *(__half2*)&g_Bh[base + 1024] = l01; *(__half2*)&g_Bh[base + 1026] = l23;
    *(__half2*)&g_Bh[base + 2048] = h01; *(__half2*)&g_Bh[base + 2050] = h23;
}

__global__ void fill_bcat(const float* __restrict__ bq, const float* __restrict__ bk) {
    int n = blockIdx.x * 256 + threadIdx.x;
    float v = 0.f;
    if (n < 1024) v = bq[n];
    else if (n < 2048) v = bk[n - 1024];
    g_bcat[n] = v;
}

// ---------------- K1: HMMA GEMM  qkv = A' @ B'^T + bcat ----------------
// BM=128, BN=256, BK=64; 3-stage cp.async pipeline; 8 warps = 4(M) x 2(N),
// warp tile 32x128. smem/stage: A 128x64 fp16 (16KB) + B 256x64 (32KB) = 48KB.
__device__ __forceinline__ void load_tile(uint32_t base, const __half* Ag, const __half* Bg, int t) {
#pragma unroll
    for (int i = 0; i < 4; i++) {
        int u = t + i * 256;
        int row = u >> 3, k = u & 7;
        cp16(base + row * 128 + ((k ^ (row & 7)) << 4),
             (const char*)(Ag + (size_t)row * KP) + k * 16);
    }
#pragma unroll
    for (int i = 0; i < 8; i++) {
        int u = t + i * 256;
        int row = u >> 3, k = u & 7;
        cp16(base + 16384 + row * 128 + ((k ^ (row & 7)) << 4),
             (const char*)(Bg + (size_t)row * KP) + k * 16);
    }
    asm volatile("cp.async.commit_group;" ::: "memory");
}

__global__ __launch_bounds__(256, 1) void gemm_hmma() {
    extern __shared__ char smem[];
    uint32_t sb = smem_u32(smem);
    int t = threadIdx.x, lane = t & 31, wid = t >> 5;
    int bm = blockIdx.y * BM, bn = blockIdx.x * BN;
    int wm = wid >> 1, wn = wid & 1;

    const __half* Ag = g_Ah + (size_t)bm * KP;
    const __half* Bg = g_Bh + (size_t)bn * KP;

    float acc[2][16][4];
#pragma unroll
    for (int mt = 0; mt < 2; mt++)
#pragma unroll
        for (int nt = 0; nt < 16; nt++)
#pragma unroll
            for (int j = 0; j < 4; j++) acc[mt][nt][j] = 0.f;

    int a_row = wm * 32 + (lane & 7) + ((lane >> 3) & 1) * 8;     // + mt*16
    int a_ch  = (lane >> 4);                                       // + ks*2
    int b_row = wn * 128 + (lane & 7) + ((lane >> 4) & 1) * 8;    // + ntp*16
    int b_ch  = (lane >> 3) & 1;                                   // + ks*2

    load_tile(sb, Ag, Bg, t);
    load_tile(sb + STG, Ag + BK, Bg + BK, t);

    for (int kt = 0; kt < NK; kt++) {
        if (kt + 2 < NK) {
            load_tile(sb + ((kt + 2) % NSTAGE) * STG,
                      Ag + (size_t)(kt + 2) * BK, Bg + (size_t)(kt + 2) * BK, t);
            asm volatile("cp.async.wait_group 2;" ::: "memory");
        } else {
            asm volatile("cp.async.wait_group 0;" ::: "memory");
        }
        __syncthreads();

        uint32_t base = sb + (kt % NSTAGE) * STG;
#pragma unroll
        for (int ks = 0; ks < 4; ks++) {
            uint32_t af[2][4];
#pragma unroll
            for (int mt = 0; mt < 2; mt++) {
                int r = a_row + mt * 16;
                uint32_t ad = base + r * 128 + (((ks * 2 + a_ch) ^ (r & 7)) << 4);
                asm volatile("ldmatrix.sync.aligned.m8n8.x4.shared.b16 {%0,%1,%2,%3}, [%4];"
                             : "=r"(af[mt][0]), "=r"(af[mt][1]), "=r"(af[mt][2]), "=r"(af[mt][3])
                             : "r"(ad));
            }
            uint32_t bf[16][2];
#pragma unroll
            for (int ntp = 0; ntp < 8; ntp++) {
                int r = b_row + ntp * 16;
                uint32_t ad = base + 16384 + r * 128 + (((ks * 2 + b_ch) ^ (r & 7)) << 4);
                asm volatile("ldmatrix.sync.aligned.m8n8.x4.shared.b16 {%0,%1,%2,%3}, [%4];"
                             : "=r"(bf[ntp * 2][0]), "=r"(bf[ntp * 2][1]),
                               "=r"(bf[ntp * 2 + 1][0]), "=r"(bf[ntp * 2 + 1][1])
                             : "r"(ad));
            }
#pragma unroll
            for (int mt = 0; mt < 2; mt++)
#pragma unroll
                for (int nt = 0; nt < 16; nt++) {
                    asm volatile(
                        "mma.sync.aligned.m16n8k16.row.col.f32.f16.f16.f32 "
                        "{%0,%1,%2,%3}, {%4,%5,%6,%7}, {%8,%9}, {%0,%1,%2,%3};"
                        : "+f"(acc[mt][nt][0]), "+f"(acc[mt][nt][1]),
                          "+f"(acc[mt][nt][2]), "+f"(acc[mt][nt][3])
                        : "r"(af[mt][0]), "r"(af[mt][1]), "r"(af[mt][2]), "r"(af[mt][3]),
                          "r"(bf[nt][0]), "r"(bf[nt][1]));
                }
        }
        __syncthreads();
    }

    // epilogue: direct float2 stores + bias
#pragma unroll
    for (int mt = 0; mt < 2; mt++)
#pragma unroll
        for (int h2 = 0; h2 < 2; h2++) {
            int row = bm + wm * 32 + mt * 16 + (lane >> 2) + h2 * 8;
#pragma unroll
            for (int nt = 0; nt < 16; nt++) {
                int col = bn + wn * 128 + nt * 8 + (lane & 3) * 2;
                float2 o;
                o.x = acc[mt][nt][h2 * 2 + 0] + g_bcat[col + 0];
                o.y = acc[mt][nt][h2 * 2 + 1] + g_bcat[col + 1];
                *(float2*)&g_qkv[(size_t)row * GN + col] = o;
            }
        }
}

// ---------------- K2: pos = log(max(relu(PE @ Wpos^T + bpos), 1e-6)) ----------------
__global__ __launch_bounds__(128)
void pos_kernel(const float* __restrict__ PEmb, const float* __restrict__ Wpos,
                const float* __restrict__ bpos) {
    __shared__ float pe[128 * 65];
    __shared__ float wpT[64 * 17];
    __shared__ float bp[16];
    int t = threadIdx.x;
    size_t base = (size_t)blockIdx.x * 128 * 64;
    for (int i = t; i < 128 * 64; i += 128)
        pe[(i >> 6) * 65 + (i & 63)] = PEmb[base + i];
    for (int i = t; i < 1024; i += 128)
        wpT[(i & 63) * 17 + (i >> 6)] = Wpos[i];
    if (t < 16) bp[t] = bpos[t];
    __syncthreads();

    float s[16];
#pragma unroll
    for (int h = 0; h < 16; h++) s[h] = 0.f;
    const float* pr = &pe[t * 65];
#pragma unroll 8
    for (int p = 0; p < 64; p++) {
        float a = pr[p];
        const float* w = &wpT[p * 17];
#pragma unroll
        for (int h = 0; h < 16; h++) s[h] += a * w[h];
    }
    int r = blockIdx.x * 128 + t;
    int bn = r / 36, m = r % 36;
    size_t ob = (size_t)bn * 16 * 36 + m;
#pragma unroll
    for (int h = 0; h < 16; h++) {
        float v = fmaxf(s[h] + bp[h], 1e-6f);
        g_poslog[ob + (size_t)h * 36] = logf(v);
    }
}

// ---------------- K3: attention per (b,h) ----------------
__global__ __launch_bounds__(256, 2)
void attn_kernel(const int* __restrict__ adj, const float* __restrict__ lbias,
                 const float* __restrict__ bout, float* __restrict__ out) {
    __shared__ float qh[36][64];
    __shared__ float khT[64][40];
    __shared__ float vp[36][64];
    __shared__ float att[36 * 36];
    int b = blockIdx.x >> 4, h = blockIdx.x & 15;
    int t = threadIdx.x;

    const float* base = g_qkv + (size_t)b * 36 * GN + h * 64;
    for (int i = t; i < 576; i += 256) {
        int n = i >> 4, c = (i & 15) << 2;
        const float* rp = base + (size_t)n * GN + c;
        float4 q4 = *(const float4*)rp;
        float4 k4 = *(const float4*)(rp + 1024);
        float4 v4 = *(const float4*)(rp + 2048);
        *(float4*)&qh[n][c] = q4;
        khT[c + 0][n] = k4.x; khT[c + 1][n] = k4.y;
        khT[c + 2][n] = k4.z; khT[c + 3][n] = k4.w;
        *(float4*)&vp[n][c] = v4;
    }
    __syncthreads();

    const float* pl = g_poslog + (size_t)b * 36 * 16 * 36 + (size_t)h * 36;
    for (int o = t; o < 324; o += 256) {
        int n = o / 9, m0 = (o % 9) << 2;
        float4 s = make_float4(0.f, 0.f, 0.f, 0.f);
#pragma unroll 8
        for (int d = 0; d < 64; d++) {
            float a = qh[n][d];
            float4 kv = *(const float4*)&khT[d][m0];
            s.x += a * kv.x; s.y += a * kv.y; s.z += a * kv.z; s.w += a * kv.w;
        }
        float sv[4] = {s.x, s.y, s.z, s.w};
        int rowg = (b * 36 + n) * 36;
#pragma unroll
        for (int r2 = 0; r2 < 4; r2++) {
            int m = m0 + r2;
            int gi = rowg + m;
            float logit = (adj[gi] > 0)
                          ? (sv[r2] * 0.125f + pl[(size_t)n * 16 * 36 + m])
                          : -9e15f;
            att[n * 36 + m] = logit + lbias[gi];
        }
    }
    __syncthreads();

    int warp = t >> 5, lane = t & 31;
    for (int n = warp; n < 36; n += 8) {
        float x1 = att[n * 36 + lane];
        float x2 = (lane < 4) ? att[n * 36 + 32 + lane] : -3e38f;
        float mx = fmaxf(x1, x2);
#pragma unroll
        for (int off = 16; off > 0; off >>= 1)
            mx = fmaxf(mx, __shfl_xor_sync(0xffffffffu, mx, off));
        float e1 = expf(x1 - mx);
        float e2 = (lane < 4) ? expf(x2 - mx) : 0.f;
        float sum = e1 + e2;
#pragma unroll
        for (int off = 16; off > 0; off >>= 1)
            sum += __shfl_xor_sync(0xffffffffu, sum, off);
        float inv = 1.f / sum;
        att[n * 36 + lane] = e1 * inv;
        if (lane < 4) att[n * 36 + 32 + lane] = e2 * inv;
    }
    __syncthreads();

    const float* bo = bout + h * 64;
    for (int o = t; o < 576; o += 256) {
        int n = o >> 4, e0 = (o & 15) << 2;
        float4 acc4 = *(const float4*)&bo[e0];
#pragma unroll 6
        for (int m = 0; m < 36; m++) {
            float a = att[n * 36 + m];
            float4 v4 = *(const float4*)&vp[m][e0];
            acc4.x += a * v4.x; acc4.y += a * v4.y;
            acc4.z += a * v4.z; acc4.w += a * v4.w;
        }
        *(float4*)&out[(size_t)(b * 36 + n) * 1024 + h * 64 + e0] = acc4;
    }
}

// ---------------- launch ----------------
extern "C" void kernel_launch(void* const* d_in, const int* in_sizes, int n_in,
                              void* d_out, int out_size) {
    const float* roi  = (const float*)d_in[0];
    const int*   adj  = (const int*)  d_in[1];
    const float* pe   = (const float*)d_in[2];
    const float* lb   = (const float*)d_in[3];
    const float* Wq   = (const float*)d_in[4];
    const float* bq   = (const float*)d_in[5];
    const float* Wk   = (const float*)d_in[6];
    const float* bk   = (const float*)d_in[7];
    const float* Wpos = (const float*)d_in[8];
    const float* bpos = (const float*)d_in[9];
    const float* Wout = (const float*)d_in[10];
    const float* bout = (const float*)d_in[11];
    float* out = (float*)d_out;

    static int smem_set = 0;
    if (!smem_set) {
        cudaFuncSetAttribute(gemm_hmma, cudaFuncAttributeMaxDynamicSharedMemorySize,
                             NSTAGE * STG);
        smem_set = 1;
    }

    conv_A<<<GM * GK / 4 / 256, 256>>>(roi);
    conv_B<<<GN * GK / 4 / 256, 256>>>(Wq, Wk, Wout);
    fill_bcat<<<GN / 256, 256>>>(bq, bk);

    dim3 gg(GN / BN, GM / BM);
    gemm_hmma<<<gg, 256, NSTAGE * STG>>>();

    pos_kernel<<<(4608 * 36) / 128, 128>>>(pe, Wpos, bpos);

    attn_kernel<<<128 * 16, 256>>>(adj, lb, bout, out);
}

// round 7
// speedup vs baseline: 2.8270x; 1.3039x over previous
#include <cuda_runtime.h>
#include <cuda_fp16.h>
#include <math.h>
#include <cstdint>

// B=128, N=NONGT=36, D=1024, H=16, DG=64, PE=64
#define GM 4608      // rows = B*N
#define GN 3072      // cols = 3*1024  [q|k|vproj]
#define GK 1024      // inner dim (fp32)
#define KP 2048      // split K' = 2*GK (fp16 segments: A=[Ah|Al], B=[Bh|Bh])
#define BM 128
#define BN 128
#define BK 64
#define NK (KP / BK)   // 32
#define STG 32768      // stage stride: A 16KB + B 16KB
#define NSTAGE 3

// ---------------- device scratch ----------------
__device__ __align__(16) __half g_Ah[(size_t)GM * KP];   // 18.9 MB [Ah|Al]
__device__ __align__(16) __half g_Bh[(size_t)GN * KP];   // 12.6 MB [Bh|Bh], [N,K'] K-major
__device__ __align__(16) float g_bcat[GN];
__device__ __align__(16) float g_qkv[(size_t)GM * GN];   // 56.6 MB
__device__ __align__(16) float g_poslog[4608 * 16 * 36]; // 10.6 MB

// ---------------- helpers ----------------
__device__ __forceinline__ uint32_t smem_u32(const void* p) {
    uint32_t a;
    asm("{ .reg .u64 t; cvta.to.shared.u64 t, %1; cvt.u32.u64 %0, t; }" : "=r"(a) : "l"(p));
    return a;
}
__device__ __forceinline__ void cp16(uint32_t d, const void* s) {
    asm volatile("cp.async.cg.shared.global [%0], [%1], 16;" :: "r"(d), "l"(s));
}

// ---------------- K0a: split A (fp32 -> fp16 h+l exact-ish) into [Ah|Al] ----------------
__global__ __launch_bounds__(256) void conv_A(const float* __restrict__ A) {
    int i = blockIdx.x * 256 + threadIdx.x;
    float4 v = ((const float4*)A)[i];
    int row = i >> 8;
    int c4 = (i & 255) << 2;
    float x[4] = {v.x, v.y, v.z, v.w};
    __half h[4], l[4];
#pragma unroll
    for (int j = 0; j < 4; j++) {
        h[j] = __float2half_rn(x[j]);
        l[j] = __float2half_rn(x[j] - __half2float(h[j]));
    }
    __half2 h01 = __halves2half2(h[0], h[1]), h23 = __halves2half2(h[2], h[3]);
    __half2 l01 = __halves2half2(l[0], l[1]), l23 = __halves2half2(l[2], l[3]);
    size_t base = (size_t)row * KP + c4;
    *(__half2*)&g_Ah[base]        = h01; *(__half2*)&g_Ah[base + 2]    = h23;
    *(__half2*)&g_Ah[base + 1024] = l01; *(__half2*)&g_Ah[base + 1026] = l23;
}

// ---------------- K0b: weights -> fp16 [Bh|Bh] ----------------
__global__ __launch_bounds__(256) void conv_B(const float* __restrict__ Wq,
                                              const float* __restrict__ Wk,
                                              const float* __restrict__ Wout) {
    int i = blockIdx.x * 256 + threadIdx.x;
    int row = i >> 8;
    int c4 = (i & 255) << 2;
    const float* src = (row < 1024) ? (Wq + (size_t)row * 1024)
                     : (row < 2048) ? (Wk + (size_t)(row - 1024) * 1024)
                                    : (Wout + (size_t)(row - 2048) * 1024);
    float4 v = *(const float4*)(src + c4);
    __half2 h01 = __halves2half2(__float2half_rn(v.x), __float2half_rn(v.y));
    __half2 h23 = __halves2half2(__float2half_rn(v.z), __float2half_rn(v.w));
    size_t base = (size_t)row * KP + c4;
    *(__half2*)&g_Bh[base]        = h01; *(__half2*)&g_Bh[base + 2]    = h23;
    *(__half2*)&g_Bh[base + 1024] = h01; *(__half2*)&g_Bh[base + 1026] = h23;
}

__global__ void fill_bcat(const float* __restrict__ bq, const float* __restrict__ bk) {
    int n = blockIdx.x * 256 + threadIdx.x;
    float v = 0.f;
    if (n < 1024) v = bq[n];
    else if (n < 2048) v = bk[n - 1024];
    g_bcat[n] = v;
}

// ---------------- K1: HMMA GEMM  qkv = A' @ B'^T + bcat ----------------
// BM=BN=128, BK=64, 3-stage cp.async, 8 warps 4(M)x2(N), warp tile 32x64, 2 CTA/SM.
__device__ __forceinline__ void load_tile(uint32_t base, const __half* Ag, const __half* Bg, int t) {
#pragma unroll
    for (int i = 0; i < 4; i++) {
        int u = t + i * 256;
        int row = u >> 3, k = u & 7;
        uint32_t sw = row * 128 + ((k ^ (row & 7)) << 4);
        cp16(base + sw, (const char*)(Ag + (size_t)row * KP) + k * 16);
        cp16(base + 16384 + sw, (const char*)(Bg + (size_t)row * KP) + k * 16);
    }
    asm volatile("cp.async.commit_group;" ::: "memory");
}

__global__ __launch_bounds__(256, 2) void gemm_hmma() {
    extern __shared__ char smem[];
    uint32_t sb = smem_u32(smem);
    int t = threadIdx.x, lane = t & 31, wid = t >> 5;
    int bm = blockIdx.y * BM, bn = blockIdx.x * BN;
    int wm = wid >> 1, wn = wid & 1;

    const __half* Ag = g_Ah + (size_t)bm * KP;
    const __half* Bg = g_Bh + (size_t)bn * KP;

    float acc[2][8][4];
#pragma unroll
    for (int mt = 0; mt < 2; mt++)
#pragma unroll
        for (int nt = 0; nt < 8; nt++)
#pragma unroll
            for (int j = 0; j < 4; j++) acc[mt][nt][j] = 0.f;

    int a_row = wm * 32 + (lane & 7) + ((lane >> 3) & 1) * 8;   // + mt*16
    int a_ch  = (lane >> 4);                                     // + ks*2
    int b_row = wn * 64 + (lane & 7) + ((lane >> 4) & 1) * 8;   // + ntp*16
    int b_ch  = (lane >> 3) & 1;                                 // + ks*2

    load_tile(sb, Ag, Bg, t);
    load_tile(sb + STG, Ag + BK, Bg + BK, t);

    for (int kt = 0; kt < NK; kt++) {
        if (kt + 2 < NK) {
            load_tile(sb + ((kt + 2) % NSTAGE) * STG,
                      Ag + (size_t)(kt + 2) * BK, Bg + (size_t)(kt + 2) * BK, t);
            asm volatile("cp.async.wait_group 2;" ::: "memory");
        } else {
            asm volatile("cp.async.wait_group 0;" ::: "memory");
        }
        __syncthreads();

        uint32_t base = sb + (kt % NSTAGE) * STG;
#pragma unroll
        for (int ks = 0; ks < 4; ks++) {
            uint32_t af[2][4];
#pragma unroll
            for (int mt = 0; mt < 2; mt++) {
                int r = a_row + mt * 16;
                uint32_t ad = base + r * 128 + (((ks * 2 + a_ch) ^ (r & 7)) << 4);
                asm volatile("ldmatrix.sync.aligned.m8n8.x4.shared.b16 {%0,%1,%2,%3}, [%4];"
                             : "=r"(af[mt][0]), "=r"(af[mt][1]), "=r"(af[mt][2]), "=r"(af[mt][3])
                             : "r"(ad));
            }
            uint32_t bf[8][2];
#pragma unroll
            for (int ntp = 0; ntp < 4; ntp++) {
                int r = b_row + ntp * 16;
                uint32_t ad = base + 16384 + r * 128 + (((ks * 2 + b_ch) ^ (r & 7)) << 4);
                asm volatile("ldmatrix.sync.aligned.m8n8.x4.shared.b16 {%0,%1,%2,%3}, [%4];"
                             : "=r"(bf[ntp * 2][0]), "=r"(bf[ntp * 2][1]),
                               "=r"(bf[ntp * 2 + 1][0]), "=r"(bf[ntp * 2 + 1][1])
                             : "r"(ad));
            }
#pragma unroll
            for (int mt = 0; mt < 2; mt++)
#pragma unroll
                for (int nt = 0; nt < 8; nt++) {
                    asm volatile(
                        "mma.sync.aligned.m16n8k16.row.col.f32.f16.f16.f32 "
                        "{%0,%1,%2,%3}, {%4,%5,%6,%7}, {%8,%9}, {%0,%1,%2,%3};"
                        : "+f"(acc[mt][nt][0]), "+f"(acc[mt][nt][1]),
                          "+f"(acc[mt][nt][2]), "+f"(acc[mt][nt][3])
                        : "r"(af[mt][0]), "r"(af[mt][1]), "r"(af[mt][2]), "r"(af[mt][3]),
                          "r"(bf[nt][0]), "r"(bf[nt][1]));
                }
        }
        __syncthreads();
    }

    // epilogue: direct float2 stores + bias
#pragma unroll
    for (int mt = 0; mt < 2; mt++)
#pragma unroll
        for (int h2 = 0; h2 < 2; h2++) {
            int row = bm + wm * 32 + mt * 16 + (lane >> 2) + h2 * 8;
#pragma unroll
            for (int nt = 0; nt < 8; nt++) {
                int col = bn + wn * 64 + nt * 8 + (lane & 3) * 2;
                float2 o;
                o.x = acc[mt][nt][h2 * 2 + 0] + g_bcat[col + 0];
                o.y = acc[mt][nt][h2 * 2 + 1] + g_bcat[col + 1];
                *(float2*)&g_qkv[(size_t)row * GN + col] = o;
            }
        }
}

// ---------------- K2: pos = log(max(relu(PE @ Wpos^T + bpos), 1e-6)) ----------------
__global__ __launch_bounds__(128)
void pos_kernel(const float* __restrict__ PEmb, const float* __restrict__ Wpos,
                const float* __restrict__ bpos) {
    __shared__ float pe[128 * 65];
    __shared__ float wpT[64 * 17];
    __shared__ float bp[16];
    int t = threadIdx.x;
    size_t base = (size_t)blockIdx.x * 128 * 64;
    for (int i = t; i < 128 * 64; i += 128)
        pe[(i >> 6) * 65 + (i & 63)] = PEmb[base + i];
    for (int i = t; i < 1024; i += 128)
        wpT[(i & 63) * 17 + (i >> 6)] = Wpos[i];
    if (t < 16) bp[t] = bpos[t];
    __syncthreads();

    float s[16];
#pragma unroll
    for (int h = 0; h < 16; h++) s[h] = 0.f;
    const float* pr = &pe[t * 65];
#pragma unroll 8
    for (int p = 0; p < 64; p++) {
        float a = pr[p];
        const float* w = &wpT[p * 17];
#pragma unroll
        for (int h = 0; h < 16; h++) s[h] += a * w[h];
    }
    int r = blockIdx.x * 128 + t;
    int bn = r / 36, m = r % 36;
    size_t ob = (size_t)bn * 16 * 36 + m;
#pragma unroll
    for (int h = 0; h < 16; h++) {
        float v = fmaxf(s[h] + bp[h], 1e-6f);
        g_poslog[ob + (size_t)h * 36] = logf(v);
    }
}

// ---------------- K3: attention per (b,h) ----------------
__global__ __launch_bounds__(256, 2)
void attn_kernel(const int* __restrict__ adj, const float* __restrict__ lbias,
                 const float* __restrict__ bout, float* __restrict__ out) {
    __shared__ float qh[36][64];
    __shared__ float khT[64][40];
    __shared__ float vp[36][64];
    __shared__ float att[36 * 36];
    int b = blockIdx.x >> 4, h = blockIdx.x & 15;
    int t = threadIdx.x;

    const float* base = g_qkv + (size_t)b * 36 * GN + h * 64;
    for (int i = t; i < 576; i += 256) {
        int n = i >> 4, c = (i & 15) << 2;
        const float* rp = base + (size_t)n * GN + c;
        float4 q4 = *(const float4*)rp;
        float4 k4 = *(const float4*)(rp + 1024);
        float4 v4 = *(const float4*)(rp + 2048);
        *(float4*)&qh[n][c] = q4;
        khT[c + 0][n] = k4.x; khT[c + 1][n] = k4.y;
        khT[c + 2][n] = k4.z; khT[c + 3][n] = k4.w;
        *(float4*)&vp[n][c] = v4;
    }
    __syncthreads();

    const float* pl = g_poslog + (size_t)b * 36 * 16 * 36 + (size_t)h * 36;
    for (int o = t; o < 324; o += 256) {
        int n = o / 9, m0 = (o % 9) << 2;
        float4 s = make_float4(0.f, 0.f, 0.f, 0.f);
#pragma unroll 8
        for (int d = 0; d < 64; d++) {
            float a = qh[n][d];
            float4 kv = *(const float4*)&khT[d][m0];
            s.x += a * kv.x; s.y += a * kv.y; s.z += a * kv.z; s.w += a * kv.w;
        }
        float sv[4] = {s.x, s.y, s.z, s.w};
        int rowg = (b * 36 + n) * 36;
#pragma unroll
        for (int r2 = 0; r2 < 4; r2++) {
            int m = m0 + r2;
            int gi = rowg + m;
            float logit = (adj[gi] > 0)
                          ? (sv[r2] * 0.125f + pl[(size_t)n * 16 * 36 + m])
                          : -9e15f;
            att[n * 36 + m] = logit + lbias[gi];
        }
    }
    __syncthreads();

    int warp = t >> 5, lane = t & 31;
    for (int n = warp; n < 36; n += 8) {
        float x1 = att[n * 36 + lane];
        float x2 = (lane < 4) ? att[n * 36 + 32 + lane] : -3e38f;
        float mx = fmaxf(x1, x2);
#pragma unroll
        for (int off = 16; off > 0; off >>= 1)
            mx = fmaxf(mx, __shfl_xor_sync(0xffffffffu, mx, off));
        float e1 = expf(x1 - mx);
        float e2 = (lane < 4) ? expf(x2 - mx) : 0.f;
        float sum = e1 + e2;
#pragma unroll
        for (int off = 16; off > 0; off >>= 1)
            sum += __shfl_xor_sync(0xffffffffu, sum, off);
        float inv = 1.f / sum;
        att[n * 36 + lane] = e1 * inv;
        if (lane < 4) att[n * 36 + 32 + lane] = e2 * inv;
    }
    __syncthreads();

    const float* bo = bout + h * 64;
    for (int o = t; o < 576; o += 256) {
        int n = o >> 4, e0 = (o & 15) << 2;
        float4 acc4 = *(const float4*)&bo[e0];
#pragma unroll 6
        for (int m = 0; m < 36; m++) {
            float a = att[n * 36 + m];
            float4 v4 = *(const float4*)&vp[m][e0];
            acc4.x += a * v4.x; acc4.y += a * v4.y;
            acc4.z += a * v4.z; acc4.w += a * v4.w;
        }
        *(float4*)&out[(size_t)(b * 36 + n) * 1024 + h * 64 + e0] = acc4;
    }
}

// ---------------- launch ----------------
extern "C" void kernel_launch(void* const* d_in, const int* in_sizes, int n_in,
                              void* d_out, int out_size) {
    const float* roi  = (const float*)d_in[0];
    const int*   adj  = (const int*)  d_in[1];
    const float* pe   = (const float*)d_in[2];
    const float* lb   = (const float*)d_in[3];
    const float* Wq   = (const float*)d_in[4];
    const float* bq   = (const float*)d_in[5];
    const float* Wk   = (const float*)d_in[6];
    const float* bk   = (const float*)d_in[7];
    const float* Wpos = (const float*)d_in[8];
    const float* bpos = (const float*)d_in[9];
    const float* Wout = (const float*)d_in[10];
    const float* bout = (const float*)d_in[11];
    float* out = (float*)d_out;

    static int smem_set = 0;
    if (!smem_set) {
        cudaFuncSetAttribute(gemm_hmma, cudaFuncAttributeMaxDynamicSharedMemorySize,
                             NSTAGE * STG);
        smem_set = 1;
    }

    conv_A<<<GM * GK / 4 / 256, 256>>>(roi);
    conv_B<<<GN * GK / 4 / 256, 256>>>(Wq, Wk, Wout);
    fill_bcat<<<GN / 256, 256>>>(bq, bk);

    dim3 gg(GN / BN, GM / BM);
    gemm_hmma<<<gg, 256, NSTAGE * STG>>>();

    pos_kernel<<<(4608 * 36) / 128, 128>>>(pe, Wpos, bpos);

    attn_kernel<<<128 * 16, 256>>>(adj, lb, bout, out);
}

// round 8
// speedup vs baseline: 4.0280x; 1.4249x over previous
#include <cuda_runtime.h>
#include <cuda_fp16.h>
#include <math.h>
#include <cstdint>

// B=128, N=NONGT=36, D=1024, H=16, DG=64, PE=64
#define GM 4608      // rows = B*N
#define GN 3072      // cols = 3*1024  [q|k|vproj]
#define GK 1024      // inner dim
#define KP 1024      // fp16 K (single term Ah @ Bh)
#define BM 128
#define BN 128
#define BK 64
#define NK (KP / BK)   // 16
#define STG 32768      // stage stride: A 16KB + B 16KB
#define NSTAGE 3

// ---------------- device scratch ----------------
__device__ __align__(16) __half g_Ah[(size_t)GM * KP];   // 9.4 MB
__device__ __align__(16) __half g_Bh[(size_t)GN * KP];   // 6.3 MB  [N,K] K-major
__device__ __align__(16) float g_bcat[GN];
__device__ __align__(16) float g_qkv[(size_t)GM * GN];   // 56.6 MB
__device__ __align__(16) float g_poslog[4608 * 16 * 36]; // 10.6 MB

// ---------------- helpers ----------------
__device__ __forceinline__ uint32_t smem_u32(const void* p) {
    uint32_t a;
    asm("{ .reg .u64 t; cvta.to.shared.u64 t, %1; cvt.u32.u64 %0, t; }" : "=r"(a) : "l"(p));
    return a;
}
__device__ __forceinline__ void cp16(uint32_t d, const void* s) {
    asm volatile("cp.async.cg.shared.global [%0], [%1], 16;" :: "r"(d), "l"(s));
}

// ---------------- K0a: A fp32 -> fp16 ----------------
__global__ __launch_bounds__(256) void conv_A(const float* __restrict__ A) {
    int i = blockIdx.x * 256 + threadIdx.x;       // float4 index over GM*GK/4
    float4 v = ((const float4*)A)[i];
    __half2 h01 = __halves2half2(__float2half_rn(v.x), __float2half_rn(v.y));
    __half2 h23 = __halves2half2(__float2half_rn(v.z), __float2half_rn(v.w));
    size_t base = (size_t)i * 4;
    *(__half2*)&g_Ah[base] = h01; *(__half2*)&g_Ah[base + 2] = h23;
}

// ---------------- K0b: weights -> fp16 ----------------
__global__ __launch_bounds__(256) void conv_B(const float* __restrict__ Wq,
                                              const float* __restrict__ Wk,
                                              const float* __restrict__ Wout) {
    int i = blockIdx.x * 256 + threadIdx.x;       // float4 index over GN*GK/4
    int row = i >> 8;
    int c4 = (i & 255) << 2;
    const float* src = (row < 1024) ? (Wq + (size_t)row * 1024)
                     : (row < 2048) ? (Wk + (size_t)(row - 1024) * 1024)
                                    : (Wout + (size_t)(row - 2048) * 1024);
    float4 v = *(const float4*)(src + c4);
    __half2 h01 = __halves2half2(__float2half_rn(v.x), __float2half_rn(v.y));
    __half2 h23 = __halves2half2(__float2half_rn(v.z), __float2half_rn(v.w));
    size_t base = (size_t)row * KP + c4;
    *(__half2*)&g_Bh[base] = h01; *(__half2*)&g_Bh[base + 2] = h23;
}

__global__ void fill_bcat(const float* __restrict__ bq, const float* __restrict__ bk) {
    int n = blockIdx.x * 256 + threadIdx.x;
    float v = 0.f;
    if (n < 1024) v = bq[n];
    else if (n < 2048) v = bk[n - 1024];
    g_bcat[n] = v;
}

// ---------------- K1: HMMA GEMM  qkv = A @ B^T + bcat ----------------
// BM=BN=128, BK=64, 3-stage cp.async, 8 warps 4(M)x2(N), warp tile 32x64, 2 CTA/SM.
__device__ __forceinline__ void load_tile(uint32_t base, const __half* Ag, const __half* Bg, int t) {
#pragma unroll
    for (int i = 0; i < 4; i++) {
        int u = t + i * 256;
        int row = u >> 3, k = u & 7;
        uint32_t sw = row * 128 + ((k ^ (row & 7)) << 4);
        cp16(base + sw, (const char*)(Ag + (size_t)row * KP) + k * 16);
        cp16(base + 16384 + sw, (const char*)(Bg + (size_t)row * KP) + k * 16);
    }
    asm volatile("cp.async.commit_group;" ::: "memory");
}

__global__ __launch_bounds__(256, 2) void gemm_hmma() {
    extern __shared__ char smem[];
    uint32_t sb = smem_u32(smem);
    int t = threadIdx.x, lane = t & 31, wid = t >> 5;
    int bm = blockIdx.y * BM, bn = blockIdx.x * BN;
    int wm = wid >> 1, wn = wid & 1;

    const __half* Ag = g_Ah + (size_t)bm * KP;
    const __half* Bg = g_Bh + (size_t)bn * KP;

    float acc[2][8][4];
#pragma unroll
    for (int mt = 0; mt < 2; mt++)
#pragma unroll
        for (int nt = 0; nt < 8; nt++)
#pragma unroll
            for (int j = 0; j < 4; j++) acc[mt][nt][j] = 0.f;

    int a_row = wm * 32 + (lane & 7) + ((lane >> 3) & 1) * 8;   // + mt*16
    int a_ch  = (lane >> 4);                                     // + ks*2
    int b_row = wn * 64 + (lane & 7) + ((lane >> 4) & 1) * 8;   // + ntp*16
    int b_ch  = (lane >> 3) & 1;                                 // + ks*2

    load_tile(sb, Ag, Bg, t);
    load_tile(sb + STG, Ag + BK, Bg + BK, t);

    for (int kt = 0; kt < NK; kt++) {
        if (kt + 2 < NK) {
            load_tile(sb + ((kt + 2) % NSTAGE) * STG,
                      Ag + (size_t)(kt + 2) * BK, Bg + (size_t)(kt + 2) * BK, t);
            asm volatile("cp.async.wait_group 2;" ::: "memory");
        } else {
            asm volatile("cp.async.wait_group 0;" ::: "memory");
        }
        __syncthreads();

        uint32_t base = sb + (kt % NSTAGE) * STG;
#pragma unroll
        for (int ks = 0; ks < 4; ks++) {
            uint32_t af[2][4];
#pragma unroll
            for (int mt = 0; mt < 2; mt++) {
                int r = a_row + mt * 16;
                uint32_t ad = base + r * 128 + (((ks * 2 + a_ch) ^ (r & 7)) << 4);
                asm volatile("ldmatrix.sync.aligned.m8n8.x4.shared.b16 {%0,%1,%2,%3}, [%4];"
                             : "=r"(af[mt][0]), "=r"(af[mt][1]), "=r"(af[mt][2]), "=r"(af[mt][3])
                             : "r"(ad));
            }
            uint32_t bf[8][2];
#pragma unroll
            for (int ntp = 0; ntp < 4; ntp++) {
                int r = b_row + ntp * 16;
                uint32_t ad = base + 16384 + r * 128 + (((ks * 2 + b_ch) ^ (r & 7)) << 4);
                asm volatile("ldmatrix.sync.aligned.m8n8.x4.shared.b16 {%0,%1,%2,%3}, [%4];"
                             : "=r"(bf[ntp * 2][0]), "=r"(bf[ntp * 2][1]),
                               "=r"(bf[ntp * 2 + 1][0]), "=r"(bf[ntp * 2 + 1][1])
                             : "r"(ad));
            }
#pragma unroll
            for (int mt = 0; mt < 2; mt++)
#pragma unroll
                for (int nt = 0; nt < 8; nt++) {
                    asm volatile(
                        "mma.sync.aligned.m16n8k16.row.col.f32.f16.f16.f32 "
                        "{%0,%1,%2,%3}, {%4,%5,%6,%7}, {%8,%9}, {%0,%1,%2,%3};"
                        : "+f"(acc[mt][nt][0]), "+f"(acc[mt][nt][1]),
                          "+f"(acc[mt][nt][2]), "+f"(acc[mt][nt][3])
                        : "r"(af[mt][0]), "r"(af[mt][1]), "r"(af[mt][2]), "r"(af[mt][3]),
                          "r"(bf[nt][0]), "r"(bf[nt][1]));
                }
        }
        __syncthreads();
    }

    // epilogue: direct float2 stores + bias
#pragma unroll
    for (int mt = 0; mt < 2; mt++)
#pragma unroll
        for (int h2 = 0; h2 < 2; h2++) {
            int row = bm + wm * 32 + mt * 16 + (lane >> 2) + h2 * 8;
#pragma unroll
            for (int nt = 0; nt < 8; nt++) {
                int col = bn + wn * 64 + nt * 8 + (lane & 3) * 2;
                float2 o;
                o.x = acc[mt][nt][h2 * 2 + 0] + g_bcat[col + 0];
                o.y = acc[mt][nt][h2 * 2 + 1] + g_bcat[col + 1];
                *(float2*)&g_qkv[(size_t)row * GN + col] = o;
            }
        }
}

// ---------------- K2: pos = log(max(relu(PE @ Wpos^T + bpos), 1e-6)) ----------------
__global__ __launch_bounds__(128)
void pos_kernel(const float* __restrict__ PEmb, const float* __restrict__ Wpos,
                const float* __restrict__ bpos) {
    __shared__ float pe[128 * 65];
    __shared__ float wpT[64 * 17];
    __shared__ float bp[16];
    int t = threadIdx.x;
    size_t base = (size_t)blockIdx.x * 128 * 64;
    for (int i = t; i < 128 * 64; i += 128)
        pe[(i >> 6) * 65 + (i & 63)] = PEmb[base + i];
    for (int i = t; i < 1024; i += 128)
        wpT[(i & 63) * 17 + (i >> 6)] = Wpos[i];
    if (t < 16) bp[t] = bpos[t];
    __syncthreads();

    float s[16];
#pragma unroll
    for (int h = 0; h < 16; h++) s[h] = 0.f;
    const float* pr = &pe[t * 65];
#pragma unroll 8
    for (int p = 0; p < 64; p++) {
        float a = pr[p];
        const float* w = &wpT[p * 17];
#pragma unroll
        for (int h = 0; h < 16; h++) s[h] += a * w[h];
    }
    int r = blockIdx.x * 128 + t;
    int bn = r / 36, m = r % 36;
    size_t ob = (size_t)bn * 16 * 36 + m;
#pragma unroll
    for (int h = 0; h < 16; h++) {
        float v = fmaxf(s[h] + bp[h], 1e-6f);
        g_poslog[ob + (size_t)h * 36] = __logf(v);
    }
}

// ---------------- K3: attention per (b,h) ----------------
__global__ __launch_bounds__(256, 2)
void attn_kernel(const int* __restrict__ adj, const float* __restrict__ lbias,
                 const float* __restrict__ bout, float* __restrict__ out) {
    __shared__ float qh[36][64];
    __shared__ float khT[64][40];
    __shared__ float vp[36][64];
    __shared__ float att[36 * 36];
    int b = blockIdx.x >> 4, h = blockIdx.x & 15;
    int t = threadIdx.x;

    const float* base = g_qkv + (size_t)b * 36 * GN + h * 64;
    for (int i = t; i < 576; i += 256) {
        int n = i >> 4, c = (i & 15) << 2;
        const float* rp = base + (size_t)n * GN + c;
        float4 q4 = *(const float4*)rp;
        float4 k4 = *(const float4*)(rp + 1024);
        float4 v4 = *(const float4*)(rp + 2048);
        *(float4*)&qh[n][c] = q4;
        khT[c + 0][n] = k4.x; khT[c + 1][n] = k4.y;
        khT[c + 2][n] = k4.z; khT[c + 3][n] = k4.w;
        *(float4*)&vp[n][c] = v4;
    }
    __syncthreads();

    // logits: 2n x 4m register tile, 162 active threads
    const float* pl = g_poslog + (size_t)b * 36 * 16 * 36 + (size_t)h * 36;
    if (t < 162) {
        int n0 = (t / 9) * 2, m0 = (t % 9) * 4;
        float4 s0 = make_float4(0.f, 0.f, 0.f, 0.f);
        float4 s1 = make_float4(0.f, 0.f, 0.f, 0.f);
#pragma unroll 8
        for (int d = 0; d < 64; d++) {
            float a0 = qh[n0][d], a1 = qh[n0 + 1][d];
            float4 kv = *(const float4*)&khT[d][m0];
            s0.x += a0 * kv.x; s0.y += a0 * kv.y; s0.z += a0 * kv.z; s0.w += a0 * kv.w;
            s1.x += a1 * kv.x; s1.y += a1 * kv.y; s1.z += a1 * kv.z; s1.w += a1 * kv.w;
        }
        float sv0[4] = {s0.x, s0.y, s0.z, s0.w};
        float sv1[4] = {s1.x, s1.y, s1.z, s1.w};
#pragma unroll
        for (int r2 = 0; r2 < 4; r2++) {
            int m = m0 + r2;
            int gi0 = (b * 36 + n0) * 36 + m;
            int gi1 = gi0 + 36;
            float l0 = (adj[gi0] > 0) ? (sv0[r2] * 0.125f + pl[(size_t)n0 * 16 * 36 + m]) : -9e15f;
            float l1 = (adj[gi1] > 0) ? (sv1[r2] * 0.125f + pl[(size_t)(n0 + 1) * 16 * 36 + m]) : -9e15f;
            att[n0 * 36 + m] = l0 + lbias[gi0];
            att[(n0 + 1) * 36 + m] = l1 + lbias[gi1];
        }
    }
    __syncthreads();

    // softmax over 36 (one warp per row)
    int warp = t >> 5, lane = t & 31;
    for (int n = warp; n < 36; n += 8) {
        float x1 = att[n * 36 + lane];
        float x2 = (lane < 4) ? att[n * 36 + 32 + lane] : -3e38f;
        float mx = fmaxf(x1, x2);
#pragma unroll
        for (int off = 16; off > 0; off >>= 1)
            mx = fmaxf(mx, __shfl_xor_sync(0xffffffffu, mx, off));
        float e1 = __expf(x1 - mx);
        float e2 = (lane < 4) ? __expf(x2 - mx) : 0.f;
        float sum = e1 + e2;
#pragma unroll
        for (int off = 16; off > 0; off >>= 1)
            sum += __shfl_xor_sync(0xffffffffu, sum, off);
        float inv = 1.f / sum;
        att[n * 36 + lane] = e1 * inv;
        if (lane < 4) att[n * 36 + 32 + lane] = e2 * inv;
    }
    __syncthreads();

    // out = att @ vp + bout : 2n x 8e register tile, 144 active threads
    const float* bo = bout + h * 64;
    if (t < 144) {
        int n0 = (t / 8) * 2, e0 = (t % 8) * 8;
        float4 a0a = *(const float4*)&bo[e0];
        float4 a0b = *(const float4*)&bo[e0 + 4];
        float4 a1a = a0a, a1b = a0b;
#pragma unroll 6
        for (int m = 0; m < 36; m++) {
            float w0 = att[n0 * 36 + m], w1 = att[(n0 + 1) * 36 + m];
            float4 va = *(const float4*)&vp[m][e0];
            float4 vb = *(const float4*)&vp[m][e0 + 4];
            a0a.x += w0 * va.x; a0a.y += w0 * va.y; a0a.z += w0 * va.z; a0a.w += w0 * va.w;
            a0b.x += w0 * vb.x; a0b.y += w0 * vb.y; a0b.z += w0 * vb.z; a0b.w += w0 * vb.w;
            a1a.x += w1 * va.x; a1a.y += w1 * va.y; a1a.z += w1 * va.z; a1a.w += w1 * va.w;
            a1b.x += w1 * vb.x; a1b.y += w1 * vb.y; a1b.z += w1 * vb.z; a1b.w += w1 * vb.w;
        }
        float* o0 = &out[(size_t)(b * 36 + n0) * 1024 + h * 64 + e0];
        *(float4*)o0 = a0a; *(float4*)(o0 + 4) = a0b;
        float* o1 = o0 + 1024;
        *(float4*)o1 = a1a; *(float4*)(o1 + 4) = a1b;
    }
}

// ---------------- launch ----------------
extern "C" void kernel_launch(void* const* d_in, const int* in_sizes, int n_in,
                              void* d_out, int out_size) {
    const float* roi  = (const float*)d_in[0];
    const int*   adj  = (const int*)  d_in[1];
    const float* pe   = (const float*)d_in[2];
    const float* lb   = (const float*)d_in[3];
    const float* Wq   = (const float*)d_in[4];
    const float* bq   = (const float*)d_in[5];
    const float* Wk   = (const float*)d_in[6];
    const float* bk   = (const float*)d_in[7];
    const float* Wpos = (const float*)d_in[8];
    const float* bpos = (const float*)d_in[9];
    const float* Wout = (const float*)d_in[10];
    const float* bout = (const float*)d_in[11];
    float* out = (float*)d_out;

    static int smem_set = 0;
    if (!smem_set) {
        cudaFuncSetAttribute(gemm_hmma, cudaFuncAttributeMaxDynamicSharedMemorySize,
                             NSTAGE * STG);
        smem_set = 1;
    }

    conv_A<<<GM * GK / 4 / 256, 256>>>(roi);
    conv_B<<<GN * GK / 4 / 256, 256>>>(Wq, Wk, Wout);
    fill_bcat<<<GN / 256, 256>>>(bq, bk);

    dim3 gg(GN / BN, GM / BM);
    gemm_hmma<<<gg, 256, NSTAGE * STG>>>();

    pos_kernel<<<(4608 * 36) / 128, 128>>>(pe, Wpos, bpos);

    attn_kernel<<<128 * 16, 256>>>(adj, lb, bout, out);
}

// round 10
// speedup vs baseline: 4.2146x; 1.0463x over previous
#include <cuda_runtime.h>
#include <cuda_fp16.h>
#include <math.h>
#include <cstdint>

// B=128, N=NONGT=36, D=1024, H=16, DG=64, PE=64
#define GM 4608      // rows = B*N
#define GN 3072      // cols = 3*1024  [q|k|vproj]
#define GK 1024      // inner dim
#define KP 1024      // fp16 K (single term Ah @ Bh)
#define BM 128
#define BN 128
#define BK 64
#define NK (KP / BK)   // 16
#define STG 32768      // stage stride: A 16KB + B 16KB
#define NSTAGE 3

// ---------------- device scratch ----------------
__device__ __align__(16) __half g_Ah[(size_t)GM * KP];   // 9.4 MB
__device__ __align__(16) __half g_Bh[(size_t)GN * KP];   // 6.3 MB  [N,K] K-major
__device__ __align__(16) float g_bcat[GN];
__device__ __align__(16) float g_qkv[(size_t)GM * GN];   // 56.6 MB
__device__ __align__(16) float g_poslog[4608 * 16 * 36]; // 10.6 MB

// ---------------- helpers ----------------
__device__ __forceinline__ uint32_t smem_u32(const void* p) {
    uint32_t a;
    asm("{ .reg .u64 t; cvta.to.shared.u64 t, %1; cvt.u32.u64 %0, t; }" : "=r"(a) : "l"(p));
    return a;
}
__device__ __forceinline__ void cp16(uint32_t d, const void* s) {
    asm volatile("cp.async.cg.shared.global [%0], [%1], 16;" :: "r"(d), "l"(s));
}

// ---------------- K0a: A fp32 -> fp16 ----------------
__global__ __launch_bounds__(256) void conv_A(const float* __restrict__ A) {
    int i = blockIdx.x * 256 + threadIdx.x;       // float4 index over GM*GK/4
    float4 v = ((const float4*)A)[i];
    __half2 h01 = __halves2half2(__float2half_rn(v.x), __float2half_rn(v.y));
    __half2 h23 = __halves2half2(__float2half_rn(v.z), __float2half_rn(v.w));
    size_t base = (size_t)i * 4;
    *(__half2*)&g_Ah[base] = h01; *(__half2*)&g_Ah[base + 2] = h23;
}

// ---------------- K0b: weights -> fp16 ----------------
__global__ __launch_bounds__(256) void conv_B(const float* __restrict__ Wq,
                                              const float* __restrict__ Wk,
                                              const float* __restrict__ Wout) {
    int i = blockIdx.x * 256 + threadIdx.x;       // float4 index over GN*GK/4
    int row = i >> 8;
    int c4 = (i & 255) << 2;
    const float* src = (row < 1024) ? (Wq + (size_t)row * 1024)
                     : (row < 2048) ? (Wk + (size_t)(row - 1024) * 1024)
                                    : (Wout + (size_t)(row - 2048) * 1024);
    float4 v = *(const float4*)(src + c4);
    __half2 h01 = __halves2half2(__float2half_rn(v.x), __float2half_rn(v.y));
    __half2 h23 = __halves2half2(__float2half_rn(v.z), __float2half_rn(v.w));
    size_t base = (size_t)row * KP + c4;
    *(__half2*)&g_Bh[base] = h01; *(__half2*)&g_Bh[base + 2] = h23;
}

__global__ void fill_bcat(const float* __restrict__ bq, const float* __restrict__ bk) {
    int n = blockIdx.x * 256 + threadIdx.x;
    float v = 0.f;
    if (n < 1024) v = bq[n];
    else if (n < 2048) v = bk[n - 1024];
    g_bcat[n] = v;
}

// ---------------- K1: HMMA GEMM  qkv = A @ B^T + bcat ----------------
__device__ __forceinline__ void load_tile(uint32_t base, const __half* Ag, const __half* Bg, int t) {
#pragma unroll
    for (int i = 0; i < 4; i++) {
        int u = t + i * 256;
        int row = u >> 3, k = u & 7;
        uint32_t sw = row * 128 + ((k ^ (row & 7)) << 4);
        cp16(base + sw, (const char*)(Ag + (size_t)row * KP) + k * 16);
        cp16(base + 16384 + sw, (const char*)(Bg + (size_t)row * KP) + k * 16);
    }
    asm volatile("cp.async.commit_group;" ::: "memory");
}

__global__ __launch_bounds__(256, 2) void gemm_hmma() {
    extern __shared__ char smem[];
    uint32_t sb = smem_u32(smem);
    int t = threadIdx.x, lane = t & 31, wid = t >> 5;
    int bm = blockIdx.y * BM, bn = blockIdx.x * BN;
    int wm = wid >> 1, wn = wid & 1;

    const __half* Ag = g_Ah + (size_t)bm * KP;
    const __half* Bg = g_Bh + (size_t)bn * KP;

    float acc[2][8][4];
#pragma unroll
    for (int mt = 0; mt < 2; mt++)
#pragma unroll
        for (int nt = 0; nt < 8; nt++)
#pragma unroll
            for (int j = 0; j < 4; j++) acc[mt][nt][j] = 0.f;

    int a_row = wm * 32 + (lane & 7) + ((lane >> 3) & 1) * 8;   // + mt*16
    int a_ch  = (lane >> 4);                                     // + ks*2
    int b_row = wn * 64 + (lane & 7) + ((lane >> 4) & 1) * 8;   // + ntp*16
    int b_ch  = (lane >> 3) & 1;                                 // + ks*2

    load_tile(sb, Ag, Bg, t);
    load_tile(sb + STG, Ag + BK, Bg + BK, t);

    for (int kt = 0; kt < NK; kt++) {
        if (kt + 2 < NK) {
            load_tile(sb + ((kt + 2) % NSTAGE) * STG,
                      Ag + (size_t)(kt + 2) * BK, Bg + (size_t)(kt + 2) * BK, t);
            asm volatile("cp.async.wait_group 2;" ::: "memory");
        } else {
            asm volatile("cp.async.wait_group 0;" ::: "memory");
        }
        __syncthreads();

        uint32_t base = sb + (kt % NSTAGE) * STG;
#pragma unroll
        for (int ks = 0; ks < 4; ks++) {
            uint32_t af[2][4];
#pragma unroll
            for (int mt = 0; mt < 2; mt++) {
                int r = a_row + mt * 16;
                uint32_t ad = base + r * 128 + (((ks * 2 + a_ch) ^ (r & 7)) << 4);
                asm volatile("ldmatrix.sync.aligned.m8n8.x4.shared.b16 {%0,%1,%2,%3}, [%4];"
                             : "=r"(af[mt][0]), "=r"(af[mt][1]), "=r"(af[mt][2]), "=r"(af[mt][3])
                             : "r"(ad));
            }
            uint32_t bf[8][2];
#pragma unroll
            for (int ntp = 0; ntp < 4; ntp++) {
                int r = b_row + ntp * 16;
                uint32_t ad = base + 16384 + r * 128 + (((ks * 2 + b_ch) ^ (r & 7)) << 4);
                asm volatile("ldmatrix.sync.aligned.m8n8.x4.shared.b16 {%0,%1,%2,%3}, [%4];"
                             : "=r"(bf[ntp * 2][0]), "=r"(bf[ntp * 2][1]),
                               "=r"(bf[ntp * 2 + 1][0]), "=r"(bf[ntp * 2 + 1][1])
                             : "r"(ad));
            }
#pragma unroll
            for (int mt = 0; mt < 2; mt++)
#pragma unroll
                for (int nt = 0; nt < 8; nt++) {
                    asm volatile(
                        "mma.sync.aligned.m16n8k16.row.col.f32.f16.f16.f32 "
                        "{%0,%1,%2,%3}, {%4,%5,%6,%7}, {%8,%9}, {%0,%1,%2,%3};"
                        : "+f"(acc[mt][nt][0]), "+f"(acc[mt][nt][1]),
                          "+f"(acc[mt][nt][2]), "+f"(acc[mt][nt][3])
                        : "r"(af[mt][0]), "r"(af[mt][1]), "r"(af[mt][2]), "r"(af[mt][3]),
                          "r"(bf[nt][0]), "r"(bf[nt][1]));
                }
        }
        __syncthreads();
    }

    // epilogue: direct float2 stores + bias
#pragma unroll
    for (int mt = 0; mt < 2; mt++)
#pragma unroll
        for (int h2 = 0; h2 < 2; h2++) {
            int row = bm + wm * 32 + mt * 16 + (lane >> 2) + h2 * 8;
#pragma unroll
            for (int nt = 0; nt < 8; nt++) {
                int col = bn + wn * 64 + nt * 8 + (lane & 3) * 2;
                float2 o;
                o.x = acc[mt][nt][h2 * 2 + 0] + g_bcat[col + 0];
                o.y = acc[mt][nt][h2 * 2 + 1] + g_bcat[col + 1];
                *(float2*)&g_qkv[(size_t)row * GN + col] = o;
            }
        }
}

// ---------------- K2: pos = log(max(relu(PE @ Wpos^T + bpos), 1e-6)) ----------------
__global__ __launch_bounds__(128)
void pos_kernel(const float* __restrict__ PEmb, const float* __restrict__ Wpos,
                const float* __restrict__ bpos) {
    __shared__ float pe[128 * 65];
    __shared__ float wpT[64 * 17];
    __shared__ float bp[16];
    int t = threadIdx.x;
    size_t base = (size_t)blockIdx.x * 128 * 64;
    for (int i = t; i < 128 * 64; i += 128)
        pe[(i >> 6) * 65 + (i & 63)] = PEmb[base + i];
    for (int i = t; i < 1024; i += 128)
        wpT[(i & 63) * 17 + (i >> 6)] = Wpos[i];
    if (t < 16) bp[t] = bpos[t];
    __syncthreads();

    float s[16];
#pragma unroll
    for (int h = 0; h < 16; h++) s[h] = 0.f;
    const float* pr = &pe[t * 65];
#pragma unroll 8
    for (int p = 0; p < 64; p++) {
        float a = pr[p];
        const float* w = &wpT[p * 17];
#pragma unroll
        for (int h = 0; h < 16; h++) s[h] += a * w[h];
    }
    int r = blockIdx.x * 128 + t;
    int bn = r / 36, m = r % 36;
    size_t ob = (size_t)bn * 16 * 36 + m;
#pragma unroll
    for (int h = 0; h < 16; h++) {
        float v = fmaxf(s[h] + bp[h], 1e-6f);
        g_poslog[ob + (size_t)h * 36] = __logf(v);
    }
}

// ---------------- K3: attention per (b,h) ----------------
__global__ __launch_bounds__(256, 4)
void attn_kernel(const int* __restrict__ adj, const float* __restrict__ lbias,
                 const float* __restrict__ bout, float* __restrict__ out) {
    __shared__ float qh[36][64];
    __shared__ float khT[64][40];
    __shared__ float vp[36][64];
    __shared__ float att[36 * 36];
    int b = blockIdx.x >> 4, h = blockIdx.x & 15;
    int t = threadIdx.x;

    const float* base = g_qkv + (size_t)b * 36 * GN + h * 64;
    for (int i = t; i < 576; i += 256) {
        int n = i >> 4, c = (i & 15) << 2;
        const float* rp = base + (size_t)n * GN + c;
        float4 q4 = *(const float4*)rp;
        float4 k4 = *(const float4*)(rp + 1024);
        float4 v4 = *(const float4*)(rp + 2048);
        *(float4*)&qh[n][c] = q4;
        khT[c + 0][n] = k4.x; khT[c + 1][n] = k4.y;
        khT[c + 2][n] = k4.z; khT[c + 3][n] = k4.w;
        *(float4*)&vp[n][c] = v4;
    }
    __syncthreads();

    // logits: 2n x 4m register tile, 162 active threads
    const float* pl = g_poslog + (size_t)b * 36 * 16 * 36 + (size_t)h * 36;
    if (t < 162) {
        int n0 = (t / 9) * 2, m0 = (t % 9) * 4;
        float4 s0 = make_float4(0.f, 0.f, 0.f, 0.f);
        float4 s1 = make_float4(0.f, 0.f, 0.f, 0.f);
#pragma unroll 8
        for (int d = 0; d < 64; d++) {
            float a0 = qh[n0][d], a1 = qh[n0 + 1][d];
            float4 kv = *(const float4*)&khT[d][m0];
            s0.x += a0 * kv.x; s0.y += a0 * kv.y; s0.z += a0 * kv.z; s0.w += a0 * kv.w;
            s1.x += a1 * kv.x; s1.y += a1 * kv.y; s1.z += a1 * kv.z; s1.w += a1 * kv.w;
        }
        float sv0[4] = {s0.x, s0.y, s0.z, s0.w};
        float sv1[4] = {s1.x, s1.y, s1.z, s1.w};
#pragma unroll
        for (int r2 = 0; r2 < 4; r2++) {
            int m = m0 + r2;
            int gi0 = (b * 36 + n0) * 36 + m;
            int gi1 = gi0 + 36;
            float l0 = (adj[gi0] > 0) ? (sv0[r2] * 0.125f + pl[(size_t)n0 * 16 * 36 + m]) : -9e15f;
            float l1 = (adj[gi1] > 0) ? (sv1[r2] * 0.125f + pl[(size_t)(n0 + 1) * 16 * 36 + m]) : -9e15f;
            att[n0 * 36 + m] = l0 + lbias[gi0];
            att[(n0 + 1) * 36 + m] = l1 + lbias[gi1];
        }
    }
    __syncthreads();

    // softmax over 36 (one warp per row)
    int warp = t >> 5, lane = t & 31;
    for (int n = warp; n < 36; n += 8) {
        float x1 = att[n * 36 + lane];
        float x2 = (lane < 4) ? att[n * 36 + 32 + lane] : -3e38f;
        float mx = fmaxf(x1, x2);
#pragma unroll
        for (int off = 16; off > 0; off >>= 1)
            mx = fmaxf(mx, __shfl_xor_sync(0xffffffffu, mx, off));
        float e1 = __expf(x1 - mx);
        float e2 = (lane < 4) ? __expf(x2 - mx) : 0.f;
        float sum = e1 + e2;
#pragma unroll
        for (int off = 16; off > 0; off >>= 1)
            sum += __shfl_xor_sync(0xffffffffu, sum, off);
        float inv = 1.f / sum;
        att[n * 36 + lane] = e1 * inv;
        if (lane < 4) att[n * 36 + 32 + lane] = e2 * inv;
    }
    __syncthreads();

    // out = att @ vp + bout : 2n x 8e register tile, 144 active threads
    const float* bo = bout + h * 64;
    if (t < 144) {
        int n0 = (t / 8) * 2, e0 = (t % 8) * 8;
        float4 a0a = *(const float4*)&bo[e0];
        float4 a0b = *(const float4*)&bo[e0 + 4];
        float4 a1a = a0a, a1b = a0b;
#pragma unroll 6
        for (int m = 0; m < 36; m++) {
            float w0 = att[n0 * 36 + m], w1 = att[(n0 + 1) * 36 + m];
            float4 va = *(const float4*)&vp[m][e0];
            float4 vb = *(const float4*)&vp[m][e0 + 4];
            a0a.x += w0 * va.x; a0a.y += w0 * va.y; a0a.z += w0 * va.z; a0a.w += w0 * va.w;
            a0b.x += w0 * vb.x; a0b.y += w0 * vb.y; a0b.z += w0 * vb.z; a0b.w += w0 * vb.w;
            a1a.x += w1 * va.x; a1a.y += w1 * va.y; a1a.z += w1 * va.z; a1a.w += w1 * va.w;
            a1b.x += w1 * vb.x; a1b.y += w1 * vb.y; a1b.z += w1 * vb.z; a1b.w += w1 * vb.w;
        }
        float* o0 = &out[(size_t)(b * 36 + n0) * 1024 + h * 64 + e0];
        *(float4*)o0 = a0a; *(float4*)(o0 + 4) = a0b;
        float* o1 = o0 + 1024;
        *(float4*)o1 = a1a; *(float4*)(o1 + 4) = a1b;
    }
}

// ---------------- launch: fork/join DAG over side streams ----------------
extern "C" void kernel_launch(void* const* d_in, const int* in_sizes, int n_in,
                              void* d_out, int out_size) {
    const float* roi  = (const float*)d_in[0];
    const int*   adj  = (const int*)  d_in[1];
    const float* pe   = (const float*)d_in[2];
    const float* lb   = (const float*)d_in[3];
    const float* Wq   = (const float*)d_in[4];
    const float* bq   = (const float*)d_in[5];
    const float* Wk   = (const float*)d_in[6];
    const float* bk   = (const float*)d_in[7];
    const float* Wpos = (const float*)d_in[8];
    const float* bpos = (const float*)d_in[9];
    const float* Wout = (const float*)d_in[10];
    const float* bout = (const float*)d_in[11];
    float* out = (float*)d_out;

    static int inited = 0;
    static cudaStream_t s1, s2;
    static cudaEvent_t eFork, eW, ePos;
    if (!inited) {
        cudaFuncSetAttribute(gemm_hmma, cudaFuncAttributeMaxDynamicSharedMemorySize,
                             NSTAGE * STG);
        cudaStreamCreateWithFlags(&s1, cudaStreamNonBlocking);
        cudaStreamCreateWithFlags(&s2, cudaStreamNonBlocking);
        cudaEventCreateWithFlags(&eFork, cudaEventDisableTiming);
        cudaEventCreateWithFlags(&eW, cudaEventDisableTiming);
        cudaEventCreateWithFlags(&ePos, cudaEventDisableTiming);
        inited = 1;
    }

    // fork side streams off the (captured) legacy stream
    cudaEventRecord(eFork, 0);
    cudaStreamWaitEvent(s1, eFork, 0);
    cudaStreamWaitEvent(s2, eFork, 0);

    // s1: weight conversion + bias pack (needed by gemm)
    conv_B<<<GN * GK / 4 / 256, 256, 0, s1>>>(Wq, Wk, Wout);
    fill_bcat<<<GN / 256, 256, 0, s1>>>(bq, bk);
    cudaEventRecord(eW, s1);

    // s2: pos MLP (needed only by attn) — overlaps conv_A + gemm
    pos_kernel<<<(4608 * 36) / 128, 128, 0, s2>>>(pe, Wpos, bpos);
    cudaEventRecord(ePos, s2);

    // main stream: A conversion, then gemm (after weights ready)
    conv_A<<<GM * GK / 4 / 256, 256>>>(roi);
    cudaStreamWaitEvent(0, eW, 0);

    dim3 gg(GN / BN, GM / BM);
    gemm_hmma<<<gg, 256, NSTAGE * STG>>>();

    // attn after gemm (stream order) and pos (event)
    cudaStreamWaitEvent(0, ePos, 0);
    attn_kernel<<<128 * 16, 256>>>(adj, lb, bout, out);
}